// round 1
// baseline (speedup 1.0000x reference)
#include <cuda_runtime.h>
#include <math.h>

// Problem constants (match reference)
#define TOLC   0.5f
#define RESC   0.03f
#define GPTS   4000
#define BATCH  128
#define NEV    64
#define HEV    128

// Per-block partials (deterministic final reduce; no atomics)
__device__ float g_part[BATCH];

__device__ __forceinline__ int lower_bound_s(const float* __restrict__ a, int n, float x) {
    int lo = 0, hi = n;
    while (lo < hi) {
        int m = (lo + hi) >> 1;
        if (a[m] < x) lo = m + 1; else hi = m;
    }
    return lo;
}

__global__ __launch_bounds__(256, 1)
void llm_main_kernel(const float* __restrict__ times0, const int* __restrict__ states0,
                     const float* __restrict__ times1, const int* __restrict__ states1,
                     const float* __restrict__ head_times, const int* __restrict__ head_states,
                     const float* __restrict__ base_p, const float* __restrict__ weights)
{
    const int b = blockIdx.x;
    const int t = threadIdx.x;

    __shared__ float sh_t0[NEV], sh_t1[NEV], sh_ht[HEV];
    __shared__ int   sh_s0[NEV], sh_s1[NEV], sh_hs[HEV];
    __shared__ float sh_L0[NEV + 1], sh_L1[NEV + 1];
    __shared__ double ps[NEV];
    __shared__ float red[256];

    if (t < NEV) {
        sh_t0[t] = times0[b * NEV + t];
        sh_s0[t] = states0[b * NEV + t];
        sh_t1[t] = times1[b * NEV + t];
        sh_s1[t] = states1[b * NEV + t];
    }
    if (t < HEV) {
        sh_ht[t] = head_times[b * HEV + t];
        sh_hs[t] = head_states[b * HEV + t];
    }
    __syncthreads();

    // ---------------- Prologue: per-batch prefix-log tables ----------------
    // Q_j = sum_i [s0_i==1][t0_i - t1_j < -TOL] exp(t0_i - t1_j)
    if (t < NEV) {
        const float t1j = sh_t1[t];
        float q = 0.f;
        #pragma unroll 8
        for (int i = 0; i < NEV; i++) {
            float d = sh_t0[i] - t1j;
            if (sh_s0[i] == 1 && d < -TOLC) q += __expf(d);
        }
        ps[t] = (sh_s1[t] == 1) ? exp(2.0 * (double)t1j) * (double)q : 0.0;
    }
    __syncthreads();
    // inclusive Hillis-Steele scan in double (64 elements)
    for (int off = 1; off < NEV; off <<= 1) {
        double add = 0.0;
        if (t < NEV && t >= off) add = ps[t - off];
        __syncthreads();
        if (t < NEV) ps[t] += add;
        __syncthreads();
    }
    if (t < NEV) {
        double p = ps[t];
        sh_L0[t + 1] = (p > 0.0) ? (float)log(p) : -INFINITY;
        if (t == 0) sh_L0[0] = -INFINITY;
    }
    __syncthreads();
    if (t < NEV) ps[t] = (sh_s0[t] == 0) ? exp((double)sh_t0[t]) : 0.0;
    __syncthreads();
    for (int off = 1; off < NEV; off <<= 1) {
        double add = 0.0;
        if (t < NEV && t >= off) add = ps[t - off];
        __syncthreads();
        if (t < NEV) ps[t] += add;
        __syncthreads();
    }
    if (t < NEV) {
        double p = ps[t];
        sh_L1[t + 1] = (p > 0.0) ? (float)log(p) : -INFINITY;
        if (t == 0) sh_L1[0] = -INFINITY;
    }
    __syncthreads();

    // ---------------- softmax(weights), base ----------------
    const float w0 = weights[0], w1 = weights[1];
    const float mw = fmaxf(w0, w1);
    const float e0 = __expf(w0 - mw), e1 = __expf(w1 - mw);
    const float inv = 1.f / (e0 + e1);
    const float wn0 = e0 * inv, wn1 = e1 * inv;
    const float base = base_p[0];

    // ---------------- Evaluation ----------------
    float lamsum = 0.f;   // sum of lam over this thread's grid points
    float logsum = 0.f;   // log-lambda at this thread's event point (if any)

    for (int g = t; g < GPTS; g += 256) {
        const float te  = (float)g * RESC;
        const float thr = te - TOLC;
        const int c   = lower_bound_s(sh_t1, NEV, thr);
        const int c1  = lower_bound_s(sh_t0, NEV, thr);
        const int cnt = lower_bound_s(sh_ht, HEV, te);
        const float feat0 = __expf(sh_L0[c]  - 2.f * te);
        const float feat1 = __expf(sh_L1[c1] - te);
        const int idx = (cnt + HEV - 1) & (HEV - 1);
        const float eff0 = (sh_hs[idx] == 0) ? 1.f : -1.f;
        const float arg = base + eff0 * (wn0 * feat0 - wn1 * feat1);
        lamsum += __expf(arg);
    }

    if (t >= 1 && t < HEV) {   // event points: head_times[:, 1:]
        const float te  = sh_ht[t];
        const float thr = te - TOLC;
        const int c   = lower_bound_s(sh_t1, NEV, thr);
        const int c1  = lower_bound_s(sh_t0, NEV, thr);
        const int cnt = lower_bound_s(sh_ht, HEV, te);
        const float feat0 = __expf(sh_L0[c]  - 2.f * te);
        const float feat1 = __expf(sh_L1[c1] - te);
        const int idx = (cnt + HEV - 1) & (HEV - 1);
        const float eff0 = (sh_hs[idx] == 0) ? 1.f : -1.f;
        logsum = base + eff0 * (wn0 * feat0 - wn1 * feat1);  // log(lam) directly
    }

    // ---------------- Block reduce: logsum - RES * lamsum ----------------
    red[t] = logsum - RESC * lamsum;
    __syncthreads();
    for (int s = 128; s > 0; s >>= 1) {
        if (t < s) red[t] += red[t + s];
        __syncthreads();
    }
    if (t == 0) g_part[b] = red[0];
}

__global__ __launch_bounds__(BATCH, 1)
void llm_reduce_kernel(float* __restrict__ out)
{
    __shared__ float red[BATCH];
    const int t = threadIdx.x;
    red[t] = g_part[t];
    __syncthreads();
    for (int s = BATCH / 2; s > 0; s >>= 1) {
        if (t < s) red[t] += red[t + s];
        __syncthreads();
    }
    if (t == 0) out[0] = red[0];
}

extern "C" void kernel_launch(void* const* d_in, const int* in_sizes, int n_in,
                              void* d_out, int out_size)
{
    const float* times0      = (const float*)d_in[0];
    const int*   states0     = (const int*)  d_in[1];
    const float* times1      = (const float*)d_in[2];
    const int*   states1     = (const int*)  d_in[3];
    const float* head_times  = (const float*)d_in[4];
    const int*   head_states = (const int*)  d_in[5];
    const float* base_p      = (const float*)d_in[6];
    const float* weights     = (const float*)d_in[7];
    float* out = (float*)d_out;

    llm_main_kernel<<<BATCH, 256>>>(times0, states0, times1, states1,
                                    head_times, head_states, base_p, weights);
    llm_reduce_kernel<<<1, BATCH>>>(out);
}

// round 2
// speedup vs baseline: 1.7070x; 1.7070x over previous
#include <cuda_runtime.h>
#include <math.h>

// Problem constants (match reference)
#define TOLC   0.5f
#define RESC   0.03f
#define GPTS   4000
#define BATCH  128
#define NEV    64
#define HEV    128
#define PER_T  16           // grid points per thread (256*16 = 4096 >= 4000)

__device__ float g_part[BATCH];
__device__ unsigned int g_cnt = 0;

__device__ __forceinline__ int lower_bound_s(const float* __restrict__ a, int n, float x) {
    int lo = 0, hi = n;
    while (lo < hi) {
        int m = (lo + hi) >> 1;
        if (a[m] < x) lo = m + 1; else hi = m;
    }
    return lo;
}

__device__ __forceinline__ float warp_sum(float v) {
    v += __shfl_down_sync(0xffffffffu, v, 16);
    v += __shfl_down_sync(0xffffffffu, v, 8);
    v += __shfl_down_sync(0xffffffffu, v, 4);
    v += __shfl_down_sync(0xffffffffu, v, 2);
    v += __shfl_down_sync(0xffffffffu, v, 1);
    return v;
}

__global__ __launch_bounds__(256, 1)
void llm_fused_kernel(const float* __restrict__ times0, const int* __restrict__ states0,
                      const float* __restrict__ times1, const int* __restrict__ states1,
                      const float* __restrict__ head_times, const int* __restrict__ head_states,
                      const float* __restrict__ base_p, const float* __restrict__ weights,
                      float* __restrict__ out)
{
    const int b = blockIdx.x;
    const int t = threadIdx.x;

    __shared__ float sh_t0[NEV], sh_t1[NEV], sh_ht[HEV];
    __shared__ int   sh_s0[NEV], sh_s1[NEV], sh_hs[HEV];
    __shared__ float sh_L0[NEV + 1], sh_L1[NEV + 1];
    __shared__ double ps0[NEV], ps1[NEV];
    __shared__ float red[8];
    __shared__ bool amLast;

    if (t < NEV) {
        sh_t0[t] = times0[b * NEV + t];
        sh_s0[t] = states0[b * NEV + t];
        sh_t1[t] = times1[b * NEV + t];
        sh_s1[t] = states1[b * NEV + t];
    }
    if (t < HEV) {
        sh_ht[t] = head_times[b * HEV + t];
        sh_hs[t] = head_states[b * HEV + t];
    }
    __syncthreads();

    // ---------------- Prologue: per-batch prefix-log tables ----------------
    // Q_j = sum_i [s0_i==1][t0_i - t1_j < -TOL] exp(t0_i - t1_j)
    if (t < NEV) {
        const float t1j = sh_t1[t];
        float q = 0.f;
        #pragma unroll 8
        for (int i = 0; i < NEV; i++) {
            float d = sh_t0[i] - t1j;
            if (sh_s0[i] == 1 && d < -TOLC) q += __expf(d);
        }
        ps0[t] = (sh_s1[t] == 1) ? exp(2.0 * (double)t1j) * (double)q : 0.0;
        ps1[t] = (sh_s0[t] == 0) ? exp((double)sh_t0[t]) : 0.0;
    }
    __syncthreads();
    // fused inclusive Hillis-Steele scans (64 elements, double)
    for (int off = 1; off < NEV; off <<= 1) {
        double a0 = 0.0, a1 = 0.0;
        if (t < NEV && t >= off) { a0 = ps0[t - off]; a1 = ps1[t - off]; }
        __syncthreads();
        if (t < NEV) { ps0[t] += a0; ps1[t] += a1; }
        __syncthreads();
    }
    if (t < NEV) {
        double p0 = ps0[t], p1 = ps1[t];
        sh_L0[t + 1] = (p0 > 0.0) ? (float)log(p0) : -INFINITY;
        sh_L1[t + 1] = (p1 > 0.0) ? (float)log(p1) : -INFINITY;
        if (t == 0) { sh_L0[0] = -INFINITY; sh_L1[0] = -INFINITY; }
    }
    __syncthreads();

    // ---------------- softmax(weights), base ----------------
    const float w0 = weights[0], w1 = weights[1];
    const float mw = fmaxf(w0, w1);
    const float e0 = __expf(w0 - mw), e1 = __expf(w1 - mw);
    const float inv = 1.f / (e0 + e1);
    const float wn0 = e0 * inv, wn1 = e1 * inv;
    const float base = base_p[0];

    // ---------------- Grid evaluation: contiguous chunk + pointer walk ----
    float lamsum = 0.f;
    const int gbeg = t * PER_T;
    if (gbeg < GPTS) {
        const int gend = min(gbeg + PER_T, GPTS);
        float te  = (float)gbeg * RESC;
        float thr = te - TOLC;
        int c   = lower_bound_s(sh_t1, NEV, thr);
        int c1  = lower_bound_s(sh_t0, NEV, thr);
        int cnt = lower_bound_s(sh_ht, HEV, te);
        float nt1 = (c   < NEV) ? sh_t1[c]   : 1e30f;
        float nt0 = (c1  < NEV) ? sh_t0[c1]  : 1e30f;
        float nht = (cnt < HEV) ? sh_ht[cnt] : 1e30f;
        float f0  = __expf(sh_L0[c]  - 2.f * te);
        float f1  = __expf(sh_L1[c1] - te);
        float eff0 = (sh_hs[(cnt + HEV - 1) & (HEV - 1)] == 0) ? 1.f : -1.f;
        const float d2 = 0.886920437f;   // exp(-2*RES)
        const float d1 = 0.970445527f;   // exp(-RES)

        #pragma unroll 4
        for (int g = gbeg; g < gend; ++g) {
            lamsum += __expf(base + eff0 * (wn0 * f0 - wn1 * f1));
            // advance to g+1
            te  = (float)(g + 1) * RESC;
            thr = te - TOLC;
            f0 *= d2;
            f1 *= d1;
            if (nt1 < thr) {
                do { c++;  nt1 = (c  < NEV) ? sh_t1[c]  : 1e30f; } while (nt1 < thr);
                f0 = __expf(sh_L0[c] - 2.f * te);
            }
            if (nt0 < thr) {
                do { c1++; nt0 = (c1 < NEV) ? sh_t0[c1] : 1e30f; } while (nt0 < thr);
                f1 = __expf(sh_L1[c1] - te);
            }
            if (nht < te) {
                do { cnt++; nht = (cnt < HEV) ? sh_ht[cnt] : 1e30f; } while (nht < te);
                eff0 = (sh_hs[(cnt + HEV - 1) & (HEV - 1)] == 0) ? 1.f : -1.f;
            }
        }
    }

    // ---------------- Event points: head_times[:, 1:] ----------------
    float logsum = 0.f;
    if (t >= 1 && t < HEV) {
        const float te  = sh_ht[t];
        const float thr = te - TOLC;
        const int c   = lower_bound_s(sh_t1, NEV, thr);
        const int c1  = lower_bound_s(sh_t0, NEV, thr);
        const int cnt = lower_bound_s(sh_ht, HEV, te);
        const float feat0 = __expf(sh_L0[c]  - 2.f * te);
        const float feat1 = __expf(sh_L1[c1] - te);
        const float eff0  = (sh_hs[(cnt + HEV - 1) & (HEV - 1)] == 0) ? 1.f : -1.f;
        logsum = base + eff0 * (wn0 * feat0 - wn1 * feat1);   // log(lam) directly
    }

    // ---------------- Block reduce (warp shuffles) ----------------
    float v = warp_sum(logsum - RESC * lamsum);
    if ((t & 31) == 0) red[t >> 5] = v;
    __syncthreads();
    if (t < 8) {
        float s = red[t];
        s += __shfl_down_sync(0xffu, s, 4);
        s += __shfl_down_sync(0xffu, s, 2);
        s += __shfl_down_sync(0xffu, s, 1);
        if (t == 0) {
            g_part[b] = s;
            __threadfence();
            unsigned int prev = atomicAdd(&g_cnt, 1u);
            amLast = (prev == (unsigned int)(gridDim.x - 1));
        }
    }
    __syncthreads();

    // ---------------- Last block: final deterministic reduce ----------------
    if (amLast) {
        __threadfence();
        float s = 0.f;
        if (t < BATCH) s = __ldcg(&g_part[t]);
        s = warp_sum(s);
        if ((t & 31) == 0) red[t >> 5] = s;
        __syncthreads();
        if (t == 0) {
            float tot = red[0] + red[1] + red[2] + red[3];
            out[0] = tot;
            g_cnt = 0;   // reset for next graph replay
        }
    }
}

extern "C" void kernel_launch(void* const* d_in, const int* in_sizes, int n_in,
                              void* d_out, int out_size)
{
    const float* times0      = (const float*)d_in[0];
    const int*   states0     = (const int*)  d_in[1];
    const float* times1      = (const float*)d_in[2];
    const int*   states1     = (const int*)  d_in[3];
    const float* head_times  = (const float*)d_in[4];
    const int*   head_states = (const int*)  d_in[5];
    const float* base_p      = (const float*)d_in[6];
    const float* weights     = (const float*)d_in[7];
    float* out = (float*)d_out;

    llm_fused_kernel<<<BATCH, 256>>>(times0, states0, times1, states1,
                                     head_times, head_states, base_p, weights, out);
}

// round 3
// speedup vs baseline: 1.9503x; 1.1425x over previous
#include <cuda_runtime.h>
#include <math.h>

#define TOLC   0.5f
#define RESC   0.03f
#define GPTS   4000
#define BATCH  128
#define NEV    64
#define HEV    128
#define NTHR   512
#define PER_T  8            // 512*8 = 4096 >= 4000

#define LOG2E_F  1.4426950408889634f
#define E_ZERO  (-100000)

__device__ float g_part[BATCH];
__device__ unsigned int g_cnt = 0;

__device__ __forceinline__ int lower_bound_s(const float* __restrict__ a, int n, float x) {
    int lo = 0, hi = n;
    while (lo < hi) {
        int m = (lo + hi) >> 1;
        if (a[m] < x) lo = m + 1; else hi = m;
    }
    return lo;
}

// (m, e) pair: value = m * 2^e with m in [1,2), or m==0 (zero)
__device__ __forceinline__ void pair_add(float& am, int& ae, float bm, int be) {
    if (bm == 0.f) return;
    if (am == 0.f) { am = bm; ae = be; return; }
    int d = ae - be;
    float m; int e;
    if (d >= 0) { m = am + ldexpf(bm, -d); e = ae; }
    else        { m = bm + ldexpf(am,  d); e = be; }
    if (m >= 2.f) { m *= 0.5f; e += 1; }
    am = m; ae = e;
}

__device__ __forceinline__ float pair_log2(float m, int e) {
    return (m > 0.f) ? ((float)e + __log2f(m)) : -INFINITY;
}

__device__ __forceinline__ float warp_sum(float v) {
    v += __shfl_down_sync(0xffffffffu, v, 16);
    v += __shfl_down_sync(0xffffffffu, v, 8);
    v += __shfl_down_sync(0xffffffffu, v, 4);
    v += __shfl_down_sync(0xffffffffu, v, 2);
    v += __shfl_down_sync(0xffffffffu, v, 1);
    return v;
}

__global__ __launch_bounds__(NTHR, 1)
void llm_fused_kernel(const float* __restrict__ times0, const int* __restrict__ states0,
                      const float* __restrict__ times1, const int* __restrict__ states1,
                      const float* __restrict__ head_times, const int* __restrict__ head_states,
                      const float* __restrict__ base_p, const float* __restrict__ weights,
                      float* __restrict__ out)
{
    const int b = blockIdx.x;
    const int t = threadIdx.x;

    __shared__ float sh_t0[NEV], sh_t1[NEV], sh_ht[HEV];
    __shared__ int   sh_s0[NEV], sh_s1[NEV], sh_hs[HEV];
    __shared__ float sh_L0[NEV + 1], sh_L1[NEV + 1];   // log2-space prefix tables
    __shared__ float sqp[128];
    __shared__ float wt_m[2]; __shared__ int wt_e[2];  // warp-0 scan totals
    __shared__ float red[NTHR / 32];
    __shared__ bool amLast;

    if (t < NEV) {
        sh_t0[t] = times0[b * NEV + t];
        sh_s0[t] = states0[b * NEV + t];
        sh_t1[t] = times1[b * NEV + t];
        sh_s1[t] = states1[b * NEV + t];
    }
    if (t < HEV) {
        sh_ht[t] = head_times[b * HEV + t];
        sh_hs[t] = head_states[b * HEV + t];
    }
    __syncthreads();

    // ---- Q_j = sum_i [s0_i==1][t0_i - t1_j < -TOL] exp(t0_i - t1_j), 128-way ----
    if (t < 128) {
        const int j  = t & 63;
        const int i0 = (t >> 6) * 32;
        const float t1j = sh_t1[j];
        float q = 0.f;
        #pragma unroll 8
        for (int i = i0; i < i0 + 32; i++) {
            float d = sh_t0[i] - t1j;
            if (sh_s0[i] == 1 && d < -TOLC) q += __expf(d);
        }
        sqp[t] = q;
    }
    __syncthreads();

    // ---- prefix scans: (mantissa, exponent) pairs + warp shuffles (t < 64) ----
    if (t < NEV) {
        const int lane = t & 31;
        const int w    = t >> 5;     // 0 or 1

        float q = sqp[t] + sqp[t + 64];
        float m0 = 0.f; int e0 = E_ZERO;
        if (sh_s1[t] == 1 && q > 0.f) {
            float x = 2.f * sh_t1[t] * LOG2E_F + __log2f(q);
            float n = floorf(x);
            m0 = exp2f(x - n); e0 = (int)n;
            if (m0 >= 2.f) { m0 *= 0.5f; e0 += 1; }
        }
        float m1 = 0.f; int e1 = E_ZERO;
        if (sh_s0[t] == 0) {
            float x = sh_t0[t] * LOG2E_F;
            float n = floorf(x);
            m1 = exp2f(x - n); e1 = (int)n;
            if (m1 >= 2.f) { m1 *= 0.5f; e1 += 1; }
        }

        #pragma unroll
        for (int off = 1; off < 32; off <<= 1) {
            float om0 = __shfl_up_sync(0xffffffffu, m0, off);
            int   oe0 = __shfl_up_sync(0xffffffffu, e0, off);
            float om1 = __shfl_up_sync(0xffffffffu, m1, off);
            int   oe1 = __shfl_up_sync(0xffffffffu, e1, off);
            if (lane >= off) {
                pair_add(m0, e0, om0, oe0);
                pair_add(m1, e1, om1, oe1);
            }
        }
        if (w == 0 && lane == 31) {
            wt_m[0] = m0; wt_e[0] = e0;
            wt_m[1] = m1; wt_e[1] = e1;
        }
        __syncwarp();
        // cross-warp combine via shared (warp1 must see warp0's total)
        // barrier across the two warps: use bar 1 scoped to 64 threads
        asm volatile("bar.sync 1, 64;" ::: "memory");
        if (w == 1) {
            pair_add(m0, e0, wt_m[0], wt_e[0]);
            pair_add(m1, e1, wt_m[1], wt_e[1]);
        }
        sh_L0[t + 1] = pair_log2(m0, e0);
        sh_L1[t + 1] = pair_log2(m1, e1);
        if (t == 0) { sh_L0[0] = -INFINITY; sh_L1[0] = -INFINITY; }
    }
    __syncthreads();

    // ---- softmax(weights), base ----
    const float w0 = weights[0], w1 = weights[1];
    const float mw = fmaxf(w0, w1);
    const float ew0 = __expf(w0 - mw), ew1 = __expf(w1 - mw);
    const float inv = 1.f / (ew0 + ew1);
    const float wn0 = ew0 * inv, wn1 = ew1 * inv;
    const float base = base_p[0];

    // ---- grid evaluation (contiguous chunk + pointer walk) ----
    float lamsum = 0.f;
    const int gbeg = t * PER_T;
    if (gbeg < GPTS) {
        const int gend = min(gbeg + PER_T, GPTS);
        float te  = (float)gbeg * RESC;
        float thr = te - TOLC;
        int c   = lower_bound_s(sh_t1, NEV, thr);
        int c1  = lower_bound_s(sh_t0, NEV, thr);
        int cnt = lower_bound_s(sh_ht, HEV, te);
        float nt1 = (c   < NEV) ? sh_t1[c]   : 1e30f;
        float nt0 = (c1  < NEV) ? sh_t0[c1]  : 1e30f;
        float nht = (cnt < HEV) ? sh_ht[cnt] : 1e30f;
        float f0  = exp2f(sh_L0[c]  - 2.f * te * LOG2E_F);
        float f1  = exp2f(sh_L1[c1] - te * LOG2E_F);
        float eff0 = (sh_hs[(cnt + HEV - 1) & (HEV - 1)] == 0) ? 1.f : -1.f;
        const float d2 = 0.886920437f;   // exp(-2*RES)
        const float d1 = 0.970445527f;   // exp(-RES)

        #pragma unroll
        for (int g = gbeg; g < gend; ++g) {
            lamsum += __expf(base + eff0 * (wn0 * f0 - wn1 * f1));
            te  = (float)(g + 1) * RESC;
            thr = te - TOLC;
            f0 *= d2;
            f1 *= d1;
            if (nt1 < thr) {
                do { c++;  nt1 = (c  < NEV) ? sh_t1[c]  : 1e30f; } while (nt1 < thr);
                f0 = exp2f(sh_L0[c] - 2.f * te * LOG2E_F);
            }
            if (nt0 < thr) {
                do { c1++; nt0 = (c1 < NEV) ? sh_t0[c1] : 1e30f; } while (nt0 < thr);
                f1 = exp2f(sh_L1[c1] - te * LOG2E_F);
            }
            if (nht < te) {
                do { cnt++; nht = (cnt < HEV) ? sh_ht[cnt] : 1e30f; } while (nht < te);
                eff0 = (sh_hs[(cnt + HEV - 1) & (HEV - 1)] == 0) ? 1.f : -1.f;
            }
        }
    }

    // ---- event points: head_times[:, 1:] ----
    float logsum = 0.f;
    if (t >= 1 && t < HEV) {
        const float te  = sh_ht[t];
        const float thr = te - TOLC;
        const int c   = lower_bound_s(sh_t1, NEV, thr);
        const int c1  = lower_bound_s(sh_t0, NEV, thr);
        const int cnt = lower_bound_s(sh_ht, HEV, te);
        const float feat0 = exp2f(sh_L0[c]  - 2.f * te * LOG2E_F);
        const float feat1 = exp2f(sh_L1[c1] - te * LOG2E_F);
        const float eff0  = (sh_hs[(cnt + HEV - 1) & (HEV - 1)] == 0) ? 1.f : -1.f;
        logsum = base + eff0 * (wn0 * feat0 - wn1 * feat1);
    }

    // ---- block reduce ----
    float v = warp_sum(logsum - RESC * lamsum);
    if ((t & 31) == 0) red[t >> 5] = v;
    __syncthreads();
    if (t < 32) {
        float s = (t < NTHR / 32) ? red[t] : 0.f;
        s = warp_sum(s);
        if (t == 0) {
            g_part[b] = s;
            __threadfence();
            unsigned int prev = atomicAdd(&g_cnt, 1u);
            amLast = (prev == (unsigned int)(gridDim.x - 1));
        }
    }
    __syncthreads();

    if (amLast) {
        __threadfence();
        float s = 0.f;
        if (t < BATCH) s = __ldcg(&g_part[t]);
        s = warp_sum(s);
        if ((t & 31) == 0) red[t >> 5] = s;
        __syncthreads();
        if (t == 0) {
            out[0] = red[0] + red[1] + red[2] + red[3];
            g_cnt = 0;   // reset for next graph replay
        }
    }
}

extern "C" void kernel_launch(void* const* d_in, const int* in_sizes, int n_in,
                              void* d_out, int out_size)
{
    const float* times0      = (const float*)d_in[0];
    const int*   states0     = (const int*)  d_in[1];
    const float* times1      = (const float*)d_in[2];
    const int*   states1     = (const int*)  d_in[3];
    const float* head_times  = (const float*)d_in[4];
    const int*   head_states = (const int*)  d_in[5];
    const float* base_p      = (const float*)d_in[6];
    const float* weights     = (const float*)d_in[7];
    float* out = (float*)d_out;

    llm_fused_kernel<<<BATCH, NTHR>>>(times0, states0, times1, states1,
                                      head_times, head_states, base_p, weights, out);
}

// round 4
// speedup vs baseline: 2.2187x; 1.1376x over previous
#include <cuda_runtime.h>
#include <math.h>

#define TOLC   0.5f
#define RESC   0.03f
#define GPTS   4000
#define BATCH  128
#define NEV    64
#define HEV    128
#define NTHR   1024
#define PER_T  4            // 1024*4 = 4096 >= 4000

#define LOG2E_F  1.4426950408889634f
#define E_ZERO  (-100000)

__device__ float g_part[BATCH];
__device__ unsigned int g_cnt = 0;

__device__ __forceinline__ int lower_bound_s(const float* __restrict__ a, int n, float x) {
    int lo = 0, hi = n;
    while (lo < hi) {
        int m = (lo + hi) >> 1;
        if (a[m] < x) lo = m + 1; else hi = m;
    }
    return lo;
}

// (m, e) pair: value = m * 2^e with m in [1,2), or m==0 (zero)
__device__ __forceinline__ void pair_add(float& am, int& ae, float bm, int be) {
    if (bm == 0.f) return;
    if (am == 0.f) { am = bm; ae = be; return; }
    int d = ae - be;
    float m; int e;
    if (d >= 0) { m = am + ldexpf(bm, -d); e = ae; }
    else        { m = bm + ldexpf(am,  d); e = be; }
    if (m >= 2.f) { m *= 0.5f; e += 1; }
    am = m; ae = e;
}

__device__ __forceinline__ float pair_log2(float m, int e) {
    return (m > 0.f) ? ((float)e + __log2f(m)) : -INFINITY;
}

__device__ __forceinline__ float warp_sum(float v) {
    v += __shfl_down_sync(0xffffffffu, v, 16);
    v += __shfl_down_sync(0xffffffffu, v, 8);
    v += __shfl_down_sync(0xffffffffu, v, 4);
    v += __shfl_down_sync(0xffffffffu, v, 2);
    v += __shfl_down_sync(0xffffffffu, v, 1);
    return v;
}

__global__ __launch_bounds__(NTHR, 1)
void llm_fused_kernel(const float* __restrict__ times0, const int* __restrict__ states0,
                      const float* __restrict__ times1, const int* __restrict__ states1,
                      const float* __restrict__ head_times, const int* __restrict__ head_states,
                      const float* __restrict__ base_p, const float* __restrict__ weights,
                      float* __restrict__ out)
{
    const int b = blockIdx.x;
    const int t = threadIdx.x;

    __shared__ float sh_t0[NEV], sh_t1[NEV], sh_ht[HEV];
    __shared__ int   sh_s0[NEV], sh_s1[NEV], sh_hs[HEV];
    __shared__ float sh_L0[NEV + 1], sh_L1[NEV + 1];   // log2-space prefix tables
    __shared__ float sqp[256];
    __shared__ float wt_m[2]; __shared__ int wt_e[2];  // warp-0 scan totals
    __shared__ float red[NTHR / 32];
    __shared__ bool amLast;

    if (t < NEV) {
        sh_t0[t] = times0[b * NEV + t];
        sh_s0[t] = states0[b * NEV + t];
        sh_t1[t] = times1[b * NEV + t];
        sh_s1[t] = states1[b * NEV + t];
    }
    if (t < HEV) {
        sh_ht[t] = head_times[b * HEV + t];
        sh_hs[t] = head_states[b * HEV + t];
    }
    __syncthreads();

    // ---- Q_j = sum_i [s0_i==1][t0_i - t1_j < -TOL] exp(t0_i - t1_j), 256-way ----
    if (t < 256) {
        const int j  = t & 63;
        const int i0 = (t >> 6) * 16;       // 4 chunks of 16
        const float t1j = sh_t1[j];
        float q = 0.f;
        #pragma unroll
        for (int i = i0; i < i0 + 16; i++) {
            float d = sh_t0[i] - t1j;
            if (sh_s0[i] == 1 && d < -TOLC) q += __expf(d);
        }
        sqp[t] = q;
    }
    __syncthreads();

    // ---- prefix scans: (mantissa, exponent) pairs + warp shuffles (t < 64) ----
    if (t < NEV) {
        const int lane = t & 31;
        const int w    = t >> 5;     // 0 or 1

        float q = (sqp[t] + sqp[t + 64]) + (sqp[t + 128] + sqp[t + 192]);
        float m0 = 0.f; int e0 = E_ZERO;
        if (sh_s1[t] == 1 && q > 0.f) {
            float x = 2.f * sh_t1[t] * LOG2E_F + __log2f(q);
            float n = floorf(x);
            m0 = exp2f(x - n); e0 = (int)n;
            if (m0 >= 2.f) { m0 *= 0.5f; e0 += 1; }
        }
        float m1 = 0.f; int e1 = E_ZERO;
        if (sh_s0[t] == 0) {
            float x = sh_t0[t] * LOG2E_F;
            float n = floorf(x);
            m1 = exp2f(x - n); e1 = (int)n;
            if (m1 >= 2.f) { m1 *= 0.5f; e1 += 1; }
        }

        #pragma unroll
        for (int off = 1; off < 32; off <<= 1) {
            float om0 = __shfl_up_sync(0xffffffffu, m0, off);
            int   oe0 = __shfl_up_sync(0xffffffffu, e0, off);
            float om1 = __shfl_up_sync(0xffffffffu, m1, off);
            int   oe1 = __shfl_up_sync(0xffffffffu, e1, off);
            if (lane >= off) {
                pair_add(m0, e0, om0, oe0);
                pair_add(m1, e1, om1, oe1);
            }
        }
        if (w == 0 && lane == 31) {
            wt_m[0] = m0; wt_e[0] = e0;
            wt_m[1] = m1; wt_e[1] = e1;
        }
        __syncwarp();
        asm volatile("bar.sync 1, 64;" ::: "memory");   // 2-warp barrier
        if (w == 1) {
            pair_add(m0, e0, wt_m[0], wt_e[0]);
            pair_add(m1, e1, wt_m[1], wt_e[1]);
        }
        sh_L0[t + 1] = pair_log2(m0, e0);
        sh_L1[t + 1] = pair_log2(m1, e1);
        if (t == 0) { sh_L0[0] = -INFINITY; sh_L1[0] = -INFINITY; }
    }
    __syncthreads();

    // ---- softmax(weights), base ----
    const float w0 = weights[0], w1 = weights[1];
    const float mw = fmaxf(w0, w1);
    const float ew0 = __expf(w0 - mw), ew1 = __expf(w1 - mw);
    const float inv = 1.f / (ew0 + ew1);
    const float wn0 = ew0 * inv, wn1 = ew1 * inv;
    const float base = base_p[0];

    // ---- grid evaluation (contiguous chunk + pointer walk) ----
    float lamsum = 0.f;
    const int gbeg = t * PER_T;
    if (gbeg < GPTS) {
        const int gend = min(gbeg + PER_T, GPTS);
        float te  = (float)gbeg * RESC;
        float thr = te - TOLC;
        int c   = lower_bound_s(sh_t1, NEV, thr);
        int c1  = lower_bound_s(sh_t0, NEV, thr);
        int cnt = lower_bound_s(sh_ht, HEV, te);
        float nt1 = (c   < NEV) ? sh_t1[c]   : 1e30f;
        float nt0 = (c1  < NEV) ? sh_t0[c1]  : 1e30f;
        float nht = (cnt < HEV) ? sh_ht[cnt] : 1e30f;
        float f0  = exp2f(sh_L0[c]  - 2.f * te * LOG2E_F);
        float f1  = exp2f(sh_L1[c1] - te * LOG2E_F);
        float eff0 = (sh_hs[(cnt + HEV - 1) & (HEV - 1)] == 0) ? 1.f : -1.f;
        const float d2 = 0.886920437f;   // exp(-2*RES)
        const float d1 = 0.970445527f;   // exp(-RES)

        #pragma unroll
        for (int g = gbeg; g < gend; ++g) {
            lamsum += __expf(base + eff0 * (wn0 * f0 - wn1 * f1));
            te  = (float)(g + 1) * RESC;
            thr = te - TOLC;
            f0 *= d2;
            f1 *= d1;
            if (nt1 < thr) {
                do { c++;  nt1 = (c  < NEV) ? sh_t1[c]  : 1e30f; } while (nt1 < thr);
                f0 = exp2f(sh_L0[c] - 2.f * te * LOG2E_F);
            }
            if (nt0 < thr) {
                do { c1++; nt0 = (c1 < NEV) ? sh_t0[c1] : 1e30f; } while (nt0 < thr);
                f1 = exp2f(sh_L1[c1] - te * LOG2E_F);
            }
            if (nht < te) {
                do { cnt++; nht = (cnt < HEV) ? sh_ht[cnt] : 1e30f; } while (nht < te);
                eff0 = (sh_hs[(cnt + HEV - 1) & (HEV - 1)] == 0) ? 1.f : -1.f;
            }
        }
    }

    // ---- event points: head_times[:, 1:].  cnt(te=ht[t]) == t  => idx = t-1 ----
    float logsum = 0.f;
    if (t >= 1 && t < HEV) {
        const float te  = sh_ht[t];
        const float thr = te - TOLC;
        const int c   = lower_bound_s(sh_t1, NEV, thr);
        const int c1  = lower_bound_s(sh_t0, NEV, thr);
        const float feat0 = exp2f(sh_L0[c]  - 2.f * te * LOG2E_F);
        const float feat1 = exp2f(sh_L1[c1] - te * LOG2E_F);
        const float eff0  = (sh_hs[t - 1] == 0) ? 1.f : -1.f;
        logsum = base + eff0 * (wn0 * feat0 - wn1 * feat1);
    }

    // ---- block reduce ----
    float v = warp_sum(logsum - RESC * lamsum);
    if ((t & 31) == 0) red[t >> 5] = v;
    __syncthreads();
    if (t < 32) {
        float s = red[t];   // NTHR/32 == 32
        s = warp_sum(s);
        if (t == 0) {
            g_part[b] = s;
            __threadfence();
            unsigned int prev = atomicAdd(&g_cnt, 1u);
            amLast = (prev == (unsigned int)(gridDim.x - 1));
        }
    }
    __syncthreads();

    if (amLast) {
        __threadfence();
        float s = 0.f;
        if (t < BATCH) s = __ldcg(&g_part[t]);
        s = warp_sum(s);
        if ((t & 31) == 0) red[t >> 5] = s;
        __syncthreads();
        if (t == 0) {
            out[0] = red[0] + red[1] + red[2] + red[3];
            g_cnt = 0;   // reset for next graph replay
        }
    }
}

extern "C" void kernel_launch(void* const* d_in, const int* in_sizes, int n_in,
                              void* d_out, int out_size)
{
    const float* times0      = (const float*)d_in[0];
    const int*   states0     = (const int*)  d_in[1];
    const float* times1      = (const float*)d_in[2];
    const int*   states1     = (const int*)  d_in[3];
    const float* head_times  = (const float*)d_in[4];
    const int*   head_states = (const int*)  d_in[5];
    const float* base_p      = (const float*)d_in[6];
    const float* weights     = (const float*)d_in[7];
    float* out = (float*)d_out;

    llm_fused_kernel<<<BATCH, NTHR>>>(times0, states0, times1, states1,
                                      head_times, head_states, base_p, weights, out);
}

// round 5
// speedup vs baseline: 2.2407x; 1.0099x over previous
#include <cuda_runtime.h>
#include <math.h>

#define TOLC   0.5f
#define RESC   0.03f
#define GPTS   4000
#define BATCH  128
#define NEV    64
#define HEV    128
#define NTHR   1024
#define PER_T  4            // 1024*4 = 4096 >= 4000

#define LOG2E_F  1.4426950408889634f
#define E_ZERO  (-100000)

__device__ float g_part[BATCH];
__device__ unsigned int g_cnt = 0;

__device__ __forceinline__ int lower_bound_s(const float* __restrict__ a, int n, float x) {
    int lo = 0, hi = n;
    while (lo < hi) {
        int m = (lo + hi) >> 1;
        if (a[m] < x) lo = m + 1; else hi = m;
    }
    return lo;
}

// (m, e) pair: value = m * 2^e with m in [1,2), or m==0 (zero)
__device__ __forceinline__ void pair_add(float& am, int& ae, float bm, int be) {
    if (bm == 0.f) return;
    if (am == 0.f) { am = bm; ae = be; return; }
    int d = ae - be;
    float m; int e;
    if (d >= 0) { m = am + ldexpf(bm, -d); e = ae; }
    else        { m = bm + ldexpf(am,  d); e = be; }
    if (m >= 2.f) { m *= 0.5f; e += 1; }
    am = m; ae = e;
}

__device__ __forceinline__ float pair_log2(float m, int e) {
    return (m > 0.f) ? ((float)e + __log2f(m)) : -INFINITY;
}

// make (m,e) from a log2-space value x
__device__ __forceinline__ void pair_from_log2(float x, float& m, int& e) {
    float n = floorf(x);
    m = exp2f(x - n); e = (int)n;
    if (m >= 2.f) { m *= 0.5f; e += 1; }
}

__device__ __forceinline__ float warp_sum(float v) {
    v += __shfl_down_sync(0xffffffffu, v, 16);
    v += __shfl_down_sync(0xffffffffu, v, 8);
    v += __shfl_down_sync(0xffffffffu, v, 4);
    v += __shfl_down_sync(0xffffffffu, v, 2);
    v += __shfl_down_sync(0xffffffffu, v, 1);
    return v;
}

__global__ __launch_bounds__(NTHR, 1)
void llm_fused_kernel(const float* __restrict__ times0, const int* __restrict__ states0,
                      const float* __restrict__ times1, const int* __restrict__ states1,
                      const float* __restrict__ head_times, const int* __restrict__ head_states,
                      const float* __restrict__ base_p, const float* __restrict__ weights,
                      float* __restrict__ out)
{
    const int b = blockIdx.x;
    const int t = threadIdx.x;

    __shared__ float sh_t0[NEV], sh_t1[NEV], sh_ht[HEV];
    __shared__ int   sh_hs[HEV];
    __shared__ float sh_P0[NEV + 1];                    // log2 prefix of exp(t0)[s0==1]
    __shared__ float sh_L0[NEV + 1], sh_L1[NEV + 1];    // log2-space prefix tables
    __shared__ float wt_m[3]; __shared__ int wt_e[3];   // warp-0 scan totals
    __shared__ float red[NTHR / 32];
    __shared__ bool amLast;

    // ---- warps 2-5 load head arrays in parallel with warp 0-1 prologue ----
    if (t >= 64 && t < 192) {
        const int j = t - 64;
        sh_ht[j] = head_times[b * HEV + j];
        sh_hs[j] = head_states[b * HEV + j];
    }

    // ================= prologue: warps 0-1 only =================
    if (t < NEV) {
        const int lane = t & 31;
        const int w    = t >> 5;

        const float t0j = times0[b * NEV + t];
        const int   s0j = states0[b * NEV + t];
        const float t1j = times1[b * NEV + t];
        const int   s1j = states1[b * NEV + t];
        sh_t0[t] = t0j;
        sh_t1[t] = t1j;

        // phase A: simultaneous pair-scans of exp(t0_j) masked by s0
        float xa = t0j * LOG2E_F;
        float ma, mb; int ea, eb;
        pair_from_log2(xa, ma, ea);
        mb = ma; eb = ea;
        if (s0j == 1) { mb = 0.f; eb = E_ZERO; }   // b: s0==0 branch (L1)
        else          { ma = 0.f; ea = E_ZERO; }   // a: s0==1 branch (P0)

        #pragma unroll
        for (int off = 1; off < 32; off <<= 1) {
            float oma = __shfl_up_sync(0xffffffffu, ma, off);
            int   oea = __shfl_up_sync(0xffffffffu, ea, off);
            float omb = __shfl_up_sync(0xffffffffu, mb, off);
            int   oeb = __shfl_up_sync(0xffffffffu, eb, off);
            if (lane >= off) {
                pair_add(ma, ea, oma, oea);
                pair_add(mb, eb, omb, oeb);
            }
        }
        if (w == 0 && lane == 31) {
            wt_m[0] = ma; wt_e[0] = ea;
            wt_m[1] = mb; wt_e[1] = eb;
        }
        asm volatile("bar.sync 1, 64;" ::: "memory");
        if (w == 1) {
            pair_add(ma, ea, wt_m[0], wt_e[0]);
            pair_add(mb, eb, wt_m[1], wt_e[1]);
        }
        sh_P0[t + 1] = pair_log2(ma, ea);
        sh_L1[t + 1] = pair_log2(mb, eb);
        if (t == 0) { sh_P0[0] = -INFINITY; sh_L1[0] = -INFINITY; sh_L0[0] = -INFINITY; }
        asm volatile("bar.sync 1, 64;" ::: "memory");

        // phase B: ps0_j = exp(t1_j) * P0[c_j]  (log2-space), c_j prefix count
        float m0 = 0.f; int e0 = E_ZERO;
        if (s1j == 1) {
            const int cj = lower_bound_s(sh_t0, NEV, t1j - TOLC);
            const float p = sh_P0[cj];
            if (p > -INFINITY) pair_from_log2(t1j * LOG2E_F + p, m0, e0);
        }

        // phase C: pair-scan of ps0 -> L0
        #pragma unroll
        for (int off = 1; off < 32; off <<= 1) {
            float om0 = __shfl_up_sync(0xffffffffu, m0, off);
            int   oe0 = __shfl_up_sync(0xffffffffu, e0, off);
            if (lane >= off) pair_add(m0, e0, om0, oe0);
        }
        if (w == 0 && lane == 31) { wt_m[2] = m0; wt_e[2] = e0; }
        asm volatile("bar.sync 1, 64;" ::: "memory");
        if (w == 1) pair_add(m0, e0, wt_m[2], wt_e[2]);
        sh_L0[t + 1] = pair_log2(m0, e0);
    }
    __syncthreads();

    // ---- softmax(weights), base ----
    const float w0 = weights[0], w1 = weights[1];
    const float mw = fmaxf(w0, w1);
    const float ew0 = __expf(w0 - mw), ew1 = __expf(w1 - mw);
    const float inv = 1.f / (ew0 + ew1);
    const float wn0 = ew0 * inv, wn1 = ew1 * inv;
    const float base = base_p[0];

    // ---- grid evaluation (contiguous chunk + pointer walk) ----
    float lamsum = 0.f;
    const int gbeg = t * PER_T;
    if (gbeg < GPTS) {
        const int gend = min(gbeg + PER_T, GPTS);
        float te  = (float)gbeg * RESC;
        float thr = te - TOLC;
        int c   = lower_bound_s(sh_t1, NEV, thr);
        int c1  = lower_bound_s(sh_t0, NEV, thr);
        int cnt = lower_bound_s(sh_ht, HEV, te);
        float nt1 = (c   < NEV) ? sh_t1[c]   : 1e30f;
        float nt0 = (c1  < NEV) ? sh_t0[c1]  : 1e30f;
        float nht = (cnt < HEV) ? sh_ht[cnt] : 1e30f;
        float f0  = exp2f(sh_L0[c]  - 2.f * te * LOG2E_F);
        float f1  = exp2f(sh_L1[c1] - te * LOG2E_F);
        float eff0 = (sh_hs[(cnt + HEV - 1) & (HEV - 1)] == 0) ? 1.f : -1.f;
        const float d2 = 0.886920437f;   // exp(-2*RES)
        const float d1 = 0.970445527f;   // exp(-RES)

        #pragma unroll
        for (int g = gbeg; g < gend; ++g) {
            lamsum += __expf(base + eff0 * (wn0 * f0 - wn1 * f1));
            te  = (float)(g + 1) * RESC;
            thr = te - TOLC;
            f0 *= d2;
            f1 *= d1;
            if (nt1 < thr) {
                do { c++;  nt1 = (c  < NEV) ? sh_t1[c]  : 1e30f; } while (nt1 < thr);
                f0 = exp2f(sh_L0[c] - 2.f * te * LOG2E_F);
            }
            if (nt0 < thr) {
                do { c1++; nt0 = (c1 < NEV) ? sh_t0[c1] : 1e30f; } while (nt0 < thr);
                f1 = exp2f(sh_L1[c1] - te * LOG2E_F);
            }
            if (nht < te) {
                do { cnt++; nht = (cnt < HEV) ? sh_ht[cnt] : 1e30f; } while (nht < te);
                eff0 = (sh_hs[(cnt + HEV - 1) & (HEV - 1)] == 0) ? 1.f : -1.f;
            }
        }
    }

    // ---- event points: head_times[:, 1:].  cnt(te=ht[t]) == t  => idx = t-1 ----
    float logsum = 0.f;
    if (t >= 1 && t < HEV) {
        const float te  = sh_ht[t];
        const float thr = te - TOLC;
        const int c   = lower_bound_s(sh_t1, NEV, thr);
        const int c1  = lower_bound_s(sh_t0, NEV, thr);
        const float feat0 = exp2f(sh_L0[c]  - 2.f * te * LOG2E_F);
        const float feat1 = exp2f(sh_L1[c1] - te * LOG2E_F);
        const float eff0  = (sh_hs[t - 1] == 0) ? 1.f : -1.f;
        logsum = base + eff0 * (wn0 * feat0 - wn1 * feat1);
    }

    // ---- block reduce ----
    float v = warp_sum(logsum - RESC * lamsum);
    if ((t & 31) == 0) red[t >> 5] = v;
    __syncthreads();
    if (t < 32) {
        float s = red[t];   // NTHR/32 == 32
        s = warp_sum(s);
        if (t == 0) {
            g_part[b] = s;
            __threadfence();
            unsigned int prev = atomicAdd(&g_cnt, 1u);
            amLast = (prev == (unsigned int)(gridDim.x - 1));
        }
    }
    __syncthreads();

    if (amLast) {
        __threadfence();
        float s = 0.f;
        if (t < BATCH) s = __ldcg(&g_part[t]);
        s = warp_sum(s);
        if ((t & 31) == 0) red[t >> 5] = s;
        __syncthreads();
        if (t == 0) {
            out[0] = red[0] + red[1] + red[2] + red[3];
            g_cnt = 0;   // reset for next graph replay
        }
    }
}

extern "C" void kernel_launch(void* const* d_in, const int* in_sizes, int n_in,
                              void* d_out, int out_size)
{
    const float* times0      = (const float*)d_in[0];
    const int*   states0     = (const int*)  d_in[1];
    const float* times1      = (const float*)d_in[2];
    const int*   states1     = (const int*)  d_in[3];
    const float* head_times  = (const float*)d_in[4];
    const int*   head_states = (const int*)  d_in[5];
    const float* base_p      = (const float*)d_in[6];
    const float* weights     = (const float*)d_in[7];
    float* out = (float*)d_out;

    llm_fused_kernel<<<BATCH, NTHR>>>(times0, states0, times1, states1,
                                      head_times, head_states, base_p, weights, out);
}

// round 6
// speedup vs baseline: 2.2632x; 1.0100x over previous
#include <cuda_runtime.h>
#include <math.h>

#define TOLC   0.5f
#define RESC   0.03f
#define GPTS   4000
#define BATCH  128
#define NEV    64
#define HEV    128
#define NTHR   1024
#define PER_T  4                 // 1024*4 = 4096 >= 4000
#define NCHUNK 1024
#define INV_CHUNKW (1.0f / 0.12f)   // 1 / (PER_T*RESC)

#define LOG2E_F  1.4426950408889634f
#define E_ZERO  (-100000)
#define FXSCALE  1073741824.0       // 2^30

__device__ unsigned long long g_acc = 0ull;
__device__ unsigned int g_cnt = 0;

__device__ __forceinline__ int lower_bound_s(const float* __restrict__ a, int n, float x) {
    int lo = 0, hi = n;
    while (lo < hi) {
        int m = (lo + hi) >> 1;
        if (a[m] < x) lo = m + 1; else hi = m;
    }
    return lo;
}

// (m, e) pair: value = m * 2^e with m in [1,2), or m==0 (zero)
__device__ __forceinline__ void pair_add(float& am, int& ae, float bm, int be) {
    if (bm == 0.f) return;
    if (am == 0.f) { am = bm; ae = be; return; }
    int d = ae - be;
    float m; int e;
    if (d >= 0) { m = am + ldexpf(bm, -d); e = ae; }
    else        { m = bm + ldexpf(am,  d); e = be; }
    if (m >= 2.f) { m *= 0.5f; e += 1; }
    am = m; ae = e;
}

__device__ __forceinline__ float pair_log2(float m, int e) {
    return (m > 0.f) ? ((float)e + __log2f(m)) : -INFINITY;
}

__device__ __forceinline__ void pair_from_log2(float x, float& m, int& e) {
    float n = floorf(x);
    m = exp2f(x - n); e = (int)n;
    if (m >= 2.f) { m *= 0.5f; e += 1; }
}

__device__ __forceinline__ float warp_sum(float v) {
    v += __shfl_down_sync(0xffffffffu, v, 16);
    v += __shfl_down_sync(0xffffffffu, v, 8);
    v += __shfl_down_sync(0xffffffffu, v, 4);
    v += __shfl_down_sync(0xffffffffu, v, 2);
    v += __shfl_down_sync(0xffffffffu, v, 1);
    return v;
}

__global__ __launch_bounds__(NTHR, 1)
void llm_fused_kernel(const float* __restrict__ times0, const int* __restrict__ states0,
                      const float* __restrict__ times1, const int* __restrict__ states1,
                      const float* __restrict__ head_times, const int* __restrict__ head_states,
                      const float* __restrict__ base_p, const float* __restrict__ weights,
                      float* __restrict__ out)
{
    const int b = blockIdx.x;
    const int t = threadIdx.x;
    const int lane = t & 31;
    const int wrp  = t >> 5;

    __shared__ float sh_t0[NEV], sh_t1[NEV], sh_ht[HEV];
    __shared__ int   sh_hs[HEV];
    __shared__ float sh_P0[NEV + 1];
    __shared__ float sh_L0[NEV + 1], sh_L1[NEV + 1];
    __shared__ int   sh_cs[NCHUNK];          // packed per-chunk event counts
    __shared__ int   sh_wtot[32];
    __shared__ float wt_m[3]; __shared__ int wt_e[3];
    __shared__ float red[32];

    // ================= phase 1: zero hist, load head arrays ==============
    sh_cs[t] = 0;
    if (t >= 64 && t < 192) {
        const int j = t - 64;
        sh_ht[j] = head_times[b * HEV + j];
        sh_hs[j] = head_states[b * HEV + j];
    }
    __syncthreads();

    // ================= phase 2: prologue (warps 0-1) || histogram =========
    if (t < NEV) {
        const int w = wrp;   // 0 or 1
        const float t0j = times0[b * NEV + t];
        const int   s0j = states0[b * NEV + t];
        const float t1j = times1[b * NEV + t];
        const int   s1j = states1[b * NEV + t];
        sh_t0[t] = t0j;
        sh_t1[t] = t1j;

        // A: dual pair-scans of exp(t0_j) masked by s0
        float xa = t0j * LOG2E_F;
        float ma, mb; int ea, eb;
        pair_from_log2(xa, ma, ea);
        mb = ma; eb = ea;
        if (s0j == 1) { mb = 0.f; eb = E_ZERO; }   // b: s0==0 (L1)
        else          { ma = 0.f; ea = E_ZERO; }   // a: s0==1 (P0)

        #pragma unroll
        for (int off = 1; off < 32; off <<= 1) {
            float oma = __shfl_up_sync(0xffffffffu, ma, off);
            int   oea = __shfl_up_sync(0xffffffffu, ea, off);
            float omb = __shfl_up_sync(0xffffffffu, mb, off);
            int   oeb = __shfl_up_sync(0xffffffffu, eb, off);
            if (lane >= off) { pair_add(ma, ea, oma, oea); pair_add(mb, eb, omb, oeb); }
        }
        if (w == 0 && lane == 31) { wt_m[0] = ma; wt_e[0] = ea; wt_m[1] = mb; wt_e[1] = eb; }
        asm volatile("bar.sync 1, 64;" ::: "memory");
        if (w == 1) { pair_add(ma, ea, wt_m[0], wt_e[0]); pair_add(mb, eb, wt_m[1], wt_e[1]); }
        sh_P0[t + 1] = pair_log2(ma, ea);
        sh_L1[t + 1] = pair_log2(mb, eb);
        if (t == 0) { sh_P0[0] = -INFINITY; sh_L1[0] = -INFINITY; sh_L0[0] = -INFINITY; }
        asm volatile("bar.sync 1, 64;" ::: "memory");

        // B: ps0_j = exp(t1_j) * P0[c_j]
        float m0 = 0.f; int e0 = E_ZERO;
        if (s1j == 1) {
            const int cj = lower_bound_s(sh_t0, NEV, t1j - TOLC);
            const float p = sh_P0[cj];
            if (p > -INFINITY) pair_from_log2(t1j * LOG2E_F + p, m0, e0);
        }
        // C: pair-scan -> L0
        #pragma unroll
        for (int off = 1; off < 32; off <<= 1) {
            float om0 = __shfl_up_sync(0xffffffffu, m0, off);
            int   oe0 = __shfl_up_sync(0xffffffffu, e0, off);
            if (lane >= off) pair_add(m0, e0, om0, oe0);
        }
        if (w == 0 && lane == 31) { wt_m[2] = m0; wt_e[2] = e0; }
        asm volatile("bar.sync 1, 64;" ::: "memory");
        if (w == 1) pair_add(m0, e0, wt_m[2], wt_e[2]);
        sh_L0[t + 1] = pair_log2(m0, e0);
    } else if (t >= 256 && t < 320) {
        // histogram: t1 activation chunks (conservatively late; entry walk fixes)
        const float v = times1[b * NEV + (t - 256)];
        int a = __float2int_rd((v + TOLC) * INV_CHUNKW) + 2;
        a = min(a, NCHUNK - 1);
        atomicAdd(&sh_cs[a], 1);
    } else if (t >= 320 && t < 384) {
        const float v = times0[b * NEV + (t - 320)];
        int a = __float2int_rd((v + TOLC) * INV_CHUNKW) + 2;
        a = min(a, NCHUNK - 1);
        atomicAdd(&sh_cs[a], 1 << 8);
    } else if (t >= 384 && t < 512) {
        const float v = head_times[b * HEV + (t - 384)];
        int a = __float2int_rd(v * INV_CHUNKW) + 2;
        a = min(a, NCHUNK - 1);
        atomicAdd(&sh_cs[a], 1 << 16);
    }
    __syncthreads();

    // ================= phase 3: packed inclusive block scan ===============
    int v = sh_cs[t];
    #pragma unroll
    for (int off = 1; off < 32; off <<= 1) {
        int ov = __shfl_up_sync(0xffffffffu, v, off);
        if (lane >= off) v += ov;
    }
    if (lane == 31) sh_wtot[wrp] = v;
    __syncthreads();
    if (t < 32) {
        int wv = sh_wtot[t];
        #pragma unroll
        for (int off = 1; off < 32; off <<= 1) {
            int ov = __shfl_up_sync(0xffffffffu, wv, off);
            if (lane >= off) wv += ov;
        }
        sh_wtot[t] = wv;
    }
    __syncthreads();
    const int cs = v + ((wrp > 0) ? sh_wtot[wrp - 1] : 0);   // inclusive count at chunk t

    // ---- softmax(weights), base ----
    const float w0 = weights[0], w1 = weights[1];
    const float mw = fmaxf(w0, w1);
    const float ew0 = __expf(w0 - mw), ew1 = __expf(w1 - mw);
    const float inv = 1.f / (ew0 + ew1);
    const float wn0 = ew0 * inv, wn1 = ew1 * inv;
    const float base = base_p[0];

    // ================= grid evaluation =================
    float lamsum = 0.f;
    const int gbeg = t * PER_T;
    if (gbeg < GPTS) {
        int c   = cs & 255;
        int c1  = (cs >> 8) & 255;
        int cnt = (cs >> 16) & 255;
        float te  = (float)gbeg * RESC;
        float thr = te - TOLC;
        // entry fix-up walks (counts were understated)
        float nt1 = (c   < NEV) ? sh_t1[c]   : 1e30f;
        while (nt1 < thr) { c++;  nt1 = (c  < NEV) ? sh_t1[c]  : 1e30f; }
        float nt0 = (c1  < NEV) ? sh_t0[c1]  : 1e30f;
        while (nt0 < thr) { c1++; nt0 = (c1 < NEV) ? sh_t0[c1] : 1e30f; }
        float nht = (cnt < HEV) ? sh_ht[cnt] : 1e30f;
        while (nht < te)  { cnt++; nht = (cnt < HEV) ? sh_ht[cnt] : 1e30f; }

        float f0  = exp2f(sh_L0[c]  - 2.f * te * LOG2E_F);
        float f1  = exp2f(sh_L1[c1] - te * LOG2E_F);
        float eff0 = (sh_hs[(cnt + HEV - 1) & (HEV - 1)] == 0) ? 1.f : -1.f;
        const float d2 = 0.886920437f;   // exp(-2*RES)
        const float d1 = 0.970445527f;   // exp(-RES)

        #pragma unroll
        for (int g = gbeg; g < gbeg + PER_T; ++g) {
            if (g > gbeg) {
                te  = (float)g * RESC;
                thr = te - TOLC;
                f0 *= d2;
                f1 *= d1;
                if (nt1 < thr || nt0 < thr || nht < te) {   // single rare slow path
                    while (nt1 < thr) { c++;  nt1 = (c  < NEV) ? sh_t1[c]  : 1e30f; }
                    while (nt0 < thr) { c1++; nt0 = (c1 < NEV) ? sh_t0[c1] : 1e30f; }
                    while (nht < te)  { cnt++; nht = (cnt < HEV) ? sh_ht[cnt] : 1e30f; }
                    f0 = exp2f(sh_L0[c]  - 2.f * te * LOG2E_F);
                    f1 = exp2f(sh_L1[c1] - te * LOG2E_F);
                    eff0 = (sh_hs[(cnt + HEV - 1) & (HEV - 1)] == 0) ? 1.f : -1.f;
                }
            }
            lamsum += __expf(base + eff0 * (wn0 * f0 - wn1 * f1));
        }
    }

    // ---- event points: head_times[:, 1:];  cnt(ht[t]) == t => idx = t-1 ----
    float logsum = 0.f;
    if (t >= 1 && t < HEV) {
        const float te  = sh_ht[t];
        const float thr = te - TOLC;
        const int c   = lower_bound_s(sh_t1, NEV, thr);
        const int c1  = lower_bound_s(sh_t0, NEV, thr);
        const float feat0 = exp2f(sh_L0[c]  - 2.f * te * LOG2E_F);
        const float feat1 = exp2f(sh_L1[c1] - te * LOG2E_F);
        const float eff0  = (sh_hs[t - 1] == 0) ? 1.f : -1.f;
        logsum = base + eff0 * (wn0 * feat0 - wn1 * feat1);
    }

    // ================= reduce: block -> fixed-point global atomic =========
    float pv = warp_sum(logsum - RESC * lamsum);
    if (lane == 0) red[wrp] = pv;
    __syncthreads();
    if (t < 32) {
        float s = red[t];
        s = warp_sum(s);
        if (t == 0) {
            long long iq = llrint((double)s * FXSCALE);
            atomicAdd(&g_acc, (unsigned long long)iq);
            __threadfence();
            unsigned int prev = atomicAdd(&g_cnt, 1u);
            if (prev == (unsigned int)(gridDim.x - 1)) {
                unsigned long long tot = atomicAdd(&g_acc, 0ull);
                out[0] = (float)((double)(long long)tot * (1.0 / FXSCALE));
                g_acc = 0ull;     // reset for next graph replay
                g_cnt = 0u;
            }
        }
    }
}

extern "C" void kernel_launch(void* const* d_in, const int* in_sizes, int n_in,
                              void* d_out, int out_size)
{
    const float* times0      = (const float*)d_in[0];
    const int*   states0     = (const int*)  d_in[1];
    const float* times1      = (const float*)d_in[2];
    const int*   states1     = (const int*)  d_in[3];
    const float* head_times  = (const float*)d_in[4];
    const int*   head_states = (const int*)  d_in[5];
    const float* base_p      = (const float*)d_in[6];
    const float* weights     = (const float*)d_in[7];
    float* out = (float*)d_out;

    llm_fused_kernel<<<BATCH, NTHR>>>(times0, states0, times1, states1,
                                      head_times, head_states, base_p, weights, out);
}